// round 14
// baseline (speedup 1.0000x reference)
#include <cuda_runtime.h>
#include <cuda_bf16.h>

#define NUM_FEATURES 64
#define MAX_CAV 5
#define NX 704
#define NY 200
#define NUM_PIXELS (NY * NX)          // 140800
#define TOTAL (MAX_CAV * NUM_PIXELS)  // 704000
#define N_PILLARS 60000
#define NGROUPS (NUM_PIXELS / 4)      // 35200 (= 1100 * 32, exact)

// Inverse map: pixel -> pillar index + 1 (0 = empty).
// Invariant: all-zero before each kernel_launch. Zeroed at module load; the
// gather kernel zeroes every nonzero entry it consumes, restoring the
// invariant each call. Output is a pure function of the current inputs.
__device__ int g_pixmap[TOTAL];

// Kernel A: scatter (pillar+1) into the pixmap (indices are a permutation -> no collisions).
__global__ void __launch_bounds__(256) pp_build_pixmap(const int* __restrict__ vc)
{
    int n = blockIdx.x * blockDim.x + threadIdx.x;
    if (n >= N_PILLARS) return;
    int4 co = __ldg(reinterpret_cast<const int4*>(vc) + n);  // (b, z, y, x)
    g_pixmap[co.x * NUM_PIXELS + co.z * NX + co.w] = n + 1;
}

// Kernel B: streaming gather + self-clearing pixmap (R9 configuration —
// measured optimum across granularity/staging/fusion probes R8-R13).
//   block = (b, 32 consecutive 4-pixel groups); warp w = channel octet.
//   Warp 0 stages the 32 pixmap int4s into smem (single warp -> minimal L1
//   pressure) and zeroes the nonzero ones. Two half-transposes per thread,
//   int32 index math, <=32 regs -> 8 blocks/SM. Warp stores = 512B contiguous.
__global__ void __launch_bounds__(256, 8) pp_gather(
    const float* __restrict__ feat,   // [N, 64]
    float*       __restrict__ out)    // [5, 64, 200, 704]
{
    __shared__ int4 s_pm[32];

    int lane = threadIdx.x & 31;
    int w    = threadIdx.x >> 5;                 // 0..7 = channel octet
    int g    = blockIdx.x * 32 + lane;           // 4-pixel group 0..NGROUPS-1
    int b    = blockIdx.z;                       // 0..4

    if (w == 0) {
        int4* pmp = reinterpret_cast<int4*>(g_pixmap) + b * NGROUPS + g;
        int4 pm = *pmp;
        s_pm[lane] = pm;
        if ((pm.x | pm.y | pm.z | pm.w) != 0)
            *pmp = make_int4(0, 0, 0, 0);        // self-clear for next call
    }
    __syncthreads();

    int4 pmv = s_pm[lane];
    int p0 = pmv.x, p1 = pmv.y, p2 = pmv.z, p3 = pmv.w;

    const float4* featv = reinterpret_cast<const float4*>(feat);
    const float4 zero = make_float4(0.f, 0.f, 0.f, 0.f);

    // 32-bit feature-row offsets (float4 units), clamped to pillar 0 for
    // empty sub-pixels (broadcast L1 hit, selected to zero).
    int c2 = 2 * w;
    int f0 = (p0 > 0 ? (p0 - 1) : 0) * (NUM_FEATURES / 4) + c2;
    int f1 = (p1 > 0 ? (p1 - 1) : 0) * (NUM_FEATURES / 4) + c2;
    int f2 = (p2 > 0 ? (p2 - 1) : 0) * (NUM_FEATURES / 4) + c2;
    int f3 = (p3 > 0 ? (p3 - 1) : 0) * (NUM_FEATURES / 4) + c2;

    // 32-bit output offset (float4 units): max 11.26M, fits easily.
    int ob = (b * NUM_FEATURES + 8 * w) * NGROUPS + g;
    float4* obase = reinterpret_cast<float4*>(out) + ob;

    // Half 1: channels [8w, 8w+4)
    {
        float4 v0 = (p0 > 0) ? __ldg(featv + f0) : zero;
        float4 v1 = (p1 > 0) ? __ldg(featv + f1) : zero;
        float4 v2 = (p2 > 0) ? __ldg(featv + f2) : zero;
        float4 v3 = (p3 > 0) ? __ldg(featv + f3) : zero;
        obase[0 * NGROUPS] = make_float4(v0.x, v1.x, v2.x, v3.x);
        obase[1 * NGROUPS] = make_float4(v0.y, v1.y, v2.y, v3.y);
        obase[2 * NGROUPS] = make_float4(v0.z, v1.z, v2.z, v3.z);
        obase[3 * NGROUPS] = make_float4(v0.w, v1.w, v2.w, v3.w);
    }

    // Half 2: channels [8w+4, 8w+8)
    {
        float4 v0 = (p0 > 0) ? __ldg(featv + f0 + 1) : zero;
        float4 v1 = (p1 > 0) ? __ldg(featv + f1 + 1) : zero;
        float4 v2 = (p2 > 0) ? __ldg(featv + f2 + 1) : zero;
        float4 v3 = (p3 > 0) ? __ldg(featv + f3 + 1) : zero;
        obase[4 * NGROUPS] = make_float4(v0.x, v1.x, v2.x, v3.x);
        obase[5 * NGROUPS] = make_float4(v0.y, v1.y, v2.y, v3.y);
        obase[6 * NGROUPS] = make_float4(v0.z, v1.z, v2.z, v3.z);
        obase[7 * NGROUPS] = make_float4(v0.w, v1.w, v2.w, v3.w);
    }
}

extern "C" void kernel_launch(void* const* d_in, const int* in_sizes, int n_in,
                              void* d_out, int out_size)
{
    const int*   vc   = (const int*)d_in[0];    // voxel_coords int32 [60000, 4]
    const float* feat = (const float*)d_in[1];  // pillar_features f32 [60000, 64]
    float* out = (float*)d_out;                 // [5, 64, 200, 704] f32

    pp_build_pixmap<<<(N_PILLARS + 255) / 256, 256>>>(vc);

    dim3 grid(NGROUPS / 32, 1, MAX_CAV);   // (1100, 1, 5)
    pp_gather<<<grid, 256>>>(feat, out);
}

// round 15
// speedup vs baseline: 1.0343x; 1.0343x over previous
#include <cuda_runtime.h>
#include <cuda_bf16.h>

#define NUM_FEATURES 64
#define MAX_CAV 5
#define NX 704
#define NY 200
#define NUM_PIXELS (NY * NX)          // 140800
#define TOTAL (MAX_CAV * NUM_PIXELS)  // 704000
#define N_PILLARS 60000
#define NGROUPS (NUM_PIXELS / 4)      // 35200 (= 1100 * 32, exact)

// Inverse map: pixel -> pillar index + 1 (0 = empty), uint16 (60001 < 65536).
// Invariant: all-zero before each kernel_launch. Zeroed at module load; the
// gather kernel zeroes every nonzero entry it consumes, restoring the
// invariant each call. Output is a pure function of the current inputs.
__device__ unsigned short g_pixmap[TOTAL];

// Kernel A: scatter (pillar+1) into the pixmap (indices are a permutation -> no collisions).
__global__ void __launch_bounds__(256) pp_build_pixmap(const int* __restrict__ vc)
{
    int n = blockIdx.x * blockDim.x + threadIdx.x;
    if (n >= N_PILLARS) return;
    int4 co = __ldg(reinterpret_cast<const int4*>(vc) + n);  // (b, z, y, x)
    g_pixmap[co.x * NUM_PIXELS + co.z * NX + co.w] = (unsigned short)(n + 1);
}

// Kernel B: streaming gather + self-clearing pixmap (R9 structure, u16 pixmap).
//   block = (b, 32 consecutive 4-pixel groups); warp w = channel octet.
//   Warp 0 stages the 32 pixmap ushort4s (8B each) into smem and zeroes the
//   nonzero ones. Two half-transposes per thread, int32 index math,
//   <=32 regs -> 8 blocks/SM. Warp stores = 512B contiguous float4.
__global__ void __launch_bounds__(256, 8) pp_gather(
    const float* __restrict__ feat,   // [N, 64]
    float*       __restrict__ out)    // [5, 64, 200, 704]
{
    __shared__ ushort4 s_pm[32];

    int lane = threadIdx.x & 31;
    int w    = threadIdx.x >> 5;                 // 0..7 = channel octet
    int g    = blockIdx.x * 32 + lane;           // 4-pixel group 0..NGROUPS-1
    int b    = blockIdx.z;                       // 0..4

    if (w == 0) {
        ushort4* pmp = reinterpret_cast<ushort4*>(g_pixmap) + b * NGROUPS + g;
        ushort4 pm = *pmp;
        s_pm[lane] = pm;
        if ((pm.x | pm.y | pm.z | pm.w) != 0)
            *pmp = make_ushort4(0, 0, 0, 0);     // self-clear for next call
    }
    __syncthreads();

    ushort4 pmv = s_pm[lane];
    int p0 = pmv.x, p1 = pmv.y, p2 = pmv.z, p3 = pmv.w;

    const float4* featv = reinterpret_cast<const float4*>(feat);
    const float4 zero = make_float4(0.f, 0.f, 0.f, 0.f);

    // 32-bit feature-row offsets (float4 units), clamped to pillar 0 for
    // empty sub-pixels (broadcast L1 hit, selected to zero).
    int c2 = 2 * w;
    int f0 = (p0 > 0 ? (p0 - 1) : 0) * (NUM_FEATURES / 4) + c2;
    int f1 = (p1 > 0 ? (p1 - 1) : 0) * (NUM_FEATURES / 4) + c2;
    int f2 = (p2 > 0 ? (p2 - 1) : 0) * (NUM_FEATURES / 4) + c2;
    int f3 = (p3 > 0 ? (p3 - 1) : 0) * (NUM_FEATURES / 4) + c2;

    // 32-bit output offset (float4 units): max 11.26M, fits easily.
    int ob = (b * NUM_FEATURES + 8 * w) * NGROUPS + g;
    float4* obase = reinterpret_cast<float4*>(out) + ob;

    // Half 1: channels [8w, 8w+4)
    {
        float4 v0 = (p0 > 0) ? __ldg(featv + f0) : zero;
        float4 v1 = (p1 > 0) ? __ldg(featv + f1) : zero;
        float4 v2 = (p2 > 0) ? __ldg(featv + f2) : zero;
        float4 v3 = (p3 > 0) ? __ldg(featv + f3) : zero;
        obase[0 * NGROUPS] = make_float4(v0.x, v1.x, v2.x, v3.x);
        obase[1 * NGROUPS] = make_float4(v0.y, v1.y, v2.y, v3.y);
        obase[2 * NGROUPS] = make_float4(v0.z, v1.z, v2.z, v3.z);
        obase[3 * NGROUPS] = make_float4(v0.w, v1.w, v2.w, v3.w);
    }

    // Half 2: channels [8w+4, 8w+8)
    {
        float4 v0 = (p0 > 0) ? __ldg(featv + f0 + 1) : zero;
        float4 v1 = (p1 > 0) ? __ldg(featv + f1 + 1) : zero;
        float4 v2 = (p2 > 0) ? __ldg(featv + f2 + 1) : zero;
        float4 v3 = (p3 > 0) ? __ldg(featv + f3 + 1) : zero;
        obase[4 * NGROUPS] = make_float4(v0.x, v1.x, v2.x, v3.x);
        obase[5 * NGROUPS] = make_float4(v0.y, v1.y, v2.y, v3.y);
        obase[6 * NGROUPS] = make_float4(v0.z, v1.z, v2.z, v3.z);
        obase[7 * NGROUPS] = make_float4(v0.w, v1.w, v2.w, v3.w);
    }
}

extern "C" void kernel_launch(void* const* d_in, const int* in_sizes, int n_in,
                              void* d_out, int out_size)
{
    const int*   vc   = (const int*)d_in[0];    // voxel_coords int32 [60000, 4]
    const float* feat = (const float*)d_in[1];  // pillar_features f32 [60000, 64]
    float* out = (float*)d_out;                 // [5, 64, 200, 704] f32

    pp_build_pixmap<<<(N_PILLARS + 255) / 256, 256>>>(vc);

    dim3 grid(NGROUPS / 32, 1, MAX_CAV);   // (1100, 1, 5)
    pp_gather<<<grid, 256>>>(feat, out);
}

// round 16
// speedup vs baseline: 1.2378x; 1.1968x over previous
#include <cuda_runtime.h>
#include <cuda_bf16.h>

#define NUM_FEATURES 64
#define MAX_CAV 5
#define NX 704
#define NY 200
#define NUM_PIXELS (NY * NX)          // 140800
#define TOTAL (MAX_CAV * NUM_PIXELS)  // 704000
#define N_PILLARS 60000
#define NGROUPS (NUM_PIXELS / 4)      // 35200 (= 1100 * 32, exact)

// Inverse map: pixel -> pillar index + 1 (0 = empty), uint16 (60001 < 65536).
// Invariant: all-zero before each kernel_launch. Zeroed at module load; the
// gather kernel zeroes every nonzero entry it consumes, restoring the
// invariant each call. Output is a pure function of the current inputs.
__device__ unsigned short g_pixmap[TOTAL];

// Kernel A: scatter (pillar+1) into the pixmap (indices are a permutation -> no collisions).
__global__ void __launch_bounds__(256) pp_build_pixmap(const int* __restrict__ vc)
{
    int n = blockIdx.x * blockDim.x + threadIdx.x;
    if (n >= N_PILLARS) return;
    int4 co = __ldg(reinterpret_cast<const int4*>(vc) + n);  // (b, z, y, x)
    g_pixmap[co.x * NUM_PIXELS + co.z * NX + co.w] = (unsigned short)(n + 1);
}

// Kernel B: streaming gather + self-clearing pixmap (R15 structure; output
// stores use .cs evict-first hints — safe now that every L2 line is fully
// written by 512B-contiguous warp stores, unlike the R4 scalar-store attempt).
__global__ void __launch_bounds__(256, 8) pp_gather(
    const float* __restrict__ feat,   // [N, 64]
    float*       __restrict__ out)    // [5, 64, 200, 704]
{
    __shared__ ushort4 s_pm[32];

    int lane = threadIdx.x & 31;
    int w    = threadIdx.x >> 5;                 // 0..7 = channel octet
    int g    = blockIdx.x * 32 + lane;           // 4-pixel group 0..NGROUPS-1
    int b    = blockIdx.z;                       // 0..4

    if (w == 0) {
        ushort4* pmp = reinterpret_cast<ushort4*>(g_pixmap) + b * NGROUPS + g;
        ushort4 pm = *pmp;
        s_pm[lane] = pm;
        if ((pm.x | pm.y | pm.z | pm.w) != 0)
            *pmp = make_ushort4(0, 0, 0, 0);     // self-clear for next call
    }
    __syncthreads();

    ushort4 pmv = s_pm[lane];
    int p0 = pmv.x, p1 = pmv.y, p2 = pmv.z, p3 = pmv.w;

    const float4* featv = reinterpret_cast<const float4*>(feat);
    const float4 zero = make_float4(0.f, 0.f, 0.f, 0.f);

    // 32-bit feature-row offsets (float4 units), clamped to pillar 0 for
    // empty sub-pixels (broadcast L1 hit, selected to zero).
    int c2 = 2 * w;
    int f0 = (p0 > 0 ? (p0 - 1) : 0) * (NUM_FEATURES / 4) + c2;
    int f1 = (p1 > 0 ? (p1 - 1) : 0) * (NUM_FEATURES / 4) + c2;
    int f2 = (p2 > 0 ? (p2 - 1) : 0) * (NUM_FEATURES / 4) + c2;
    int f3 = (p3 > 0 ? (p3 - 1) : 0) * (NUM_FEATURES / 4) + c2;

    // 32-bit output offset (float4 units): max 11.26M, fits easily.
    int ob = (b * NUM_FEATURES + 8 * w) * NGROUPS + g;
    float4* obase = reinterpret_cast<float4*>(out) + ob;

    // Half 1: channels [8w, 8w+4)
    {
        float4 v0 = (p0 > 0) ? __ldg(featv + f0) : zero;
        float4 v1 = (p1 > 0) ? __ldg(featv + f1) : zero;
        float4 v2 = (p2 > 0) ? __ldg(featv + f2) : zero;
        float4 v3 = (p3 > 0) ? __ldg(featv + f3) : zero;
        __stcs(obase + 0 * NGROUPS, make_float4(v0.x, v1.x, v2.x, v3.x));
        __stcs(obase + 1 * NGROUPS, make_float4(v0.y, v1.y, v2.y, v3.y));
        __stcs(obase + 2 * NGROUPS, make_float4(v0.z, v1.z, v2.z, v3.z));
        __stcs(obase + 3 * NGROUPS, make_float4(v0.w, v1.w, v2.w, v3.w));
    }

    // Half 2: channels [8w+4, 8w+8)
    {
        float4 v0 = (p0 > 0) ? __ldg(featv + f0 + 1) : zero;
        float4 v1 = (p1 > 0) ? __ldg(featv + f1 + 1) : zero;
        float4 v2 = (p2 > 0) ? __ldg(featv + f2 + 1) : zero;
        float4 v3 = (p3 > 0) ? __ldg(featv + f3 + 1) : zero;
        __stcs(obase + 4 * NGROUPS, make_float4(v0.x, v1.x, v2.x, v3.x));
        __stcs(obase + 5 * NGROUPS, make_float4(v0.y, v1.y, v2.y, v3.y));
        __stcs(obase + 6 * NGROUPS, make_float4(v0.z, v1.z, v2.z, v3.z));
        __stcs(obase + 7 * NGROUPS, make_float4(v0.w, v1.w, v2.w, v3.w));
    }
}

extern "C" void kernel_launch(void* const* d_in, const int* in_sizes, int n_in,
                              void* d_out, int out_size)
{
    const int*   vc   = (const int*)d_in[0];    // voxel_coords int32 [60000, 4]
    const float* feat = (const float*)d_in[1];  // pillar_features f32 [60000, 64]
    float* out = (float*)d_out;                 // [5, 64, 200, 704] f32

    pp_build_pixmap<<<(N_PILLARS + 255) / 256, 256>>>(vc);

    dim3 grid(NGROUPS / 32, 1, MAX_CAV);   // (1100, 1, 5)
    pp_gather<<<grid, 256>>>(feat, out);
}